// round 4
// baseline (speedup 1.0000x reference)
#include <cuda_runtime.h>
#include <mma.h>
#include <cstdint>

using namespace nvcuda;

#define BATCH 2
#define SEQ   2048
#define MEMN  256
#define DIM   1024
#define HEADS 16
#define DH    64
#define ROWS  (BATCH*SEQ)     // 4096
#define MROWS (BATCH*MEMN)    // 512
#define KTOT  (SEQ+MEMN)      // 2304

// -------- scratch (static device globals; no allocation allowed) --------
static __device__ float g_xn [ROWS * DIM];
static __device__ float g_q  [ROWS * DIM];
static __device__ float g_kv [ROWS * 2 * DIM];
static __device__ float g_mem[MROWS * DIM];
static __device__ float g_att[ROWS * DIM];

// tf32 round-split: f = hi + lo, both exact tf32 values (cvt.rna = RN to tf32)
__device__ __forceinline__ void tf32_split(float f, float& hi, float& lo) {
    uint32_t u; asm("cvt.rna.tf32.f32 %0, %1;" : "=r"(u) : "f"(f));
    hi = __uint_as_float(u);
    float r = f - hi;
    uint32_t v; asm("cvt.rna.tf32.f32 %0, %1;" : "=r"(v) : "f"(r));
    lo = __uint_as_float(v);
}

// =======================================================================
// LayerNorm: one block per row, 256 threads, one float4 per thread
// =======================================================================
__global__ void __launch_bounds__(256) ln_kernel(
    const float* __restrict__ x, const float* __restrict__ gamma,
    const float* __restrict__ beta, float* __restrict__ out)
{
    const int row = blockIdx.x;
    const int t   = threadIdx.x;
    float4 v = ((const float4*)(x + (size_t)row * DIM))[t];
    float s  = v.x + v.y + v.z + v.w;
    float ss = v.x*v.x + v.y*v.y + v.z*v.z + v.w*v.w;
    #pragma unroll
    for (int o = 16; o > 0; o >>= 1) {
        s  += __shfl_xor_sync(0xffffffffu, s,  o);
        ss += __shfl_xor_sync(0xffffffffu, ss, o);
    }
    __shared__ float sums[8], sqs[8];
    if ((t & 31) == 0) { sums[t >> 5] = s; sqs[t >> 5] = ss; }
    __syncthreads();
    s = 0.f; ss = 0.f;
    #pragma unroll
    for (int i = 0; i < 8; i++) { s += sums[i]; ss += sqs[i]; }
    const float mean = s * (1.0f / DIM);
    const float var  = ss * (1.0f / DIM) - mean * mean;
    const float rstd = rsqrtf(var + 1e-5f);
    float4 g4 = ((const float4*)gamma)[t];
    float4 b4 = ((const float4*)beta)[t];
    float4 o;
    o.x = (v.x - mean) * rstd * g4.x + b4.x;
    o.y = (v.y - mean) * rstd * g4.y + b4.y;
    o.z = (v.z - mean) * rstd * g4.z + b4.z;
    o.w = (v.w - mean) * rstd * g4.w + b4.w;
    ((float4*)(out + (size_t)row * DIM))[t] = o;
}

// =======================================================================
// WMMA tf32 3x-compensated GEMM: C[M,N] = A[M,K] @ B[K,N]
// 128x128 block, BK=16, 256 threads (8 warps = 4m x 2n, warp = 32x64).
// A, B are fp32 in global; split to tf32 hi/lo in-kernel.
// Double-buffered smem.
// =======================================================================
#define LDA 20    // padded lead dim for A tiles (128 rows x 16 k)
#define LDB 132   // padded lead dim for B tiles (16 k x 128 n)
#define SA_FLOATS (128 * LDA)          // 2560
#define SB_FLOATS (16 * LDB)           // 2112
#define GSMEM ((2 * SA_FLOATS * 2 + 2 * SB_FLOATS * 2) * 4)  // 74752 B

__global__ void __launch_bounds__(256) gemm_wmma3x(
    const float* __restrict__ A, const float* __restrict__ B,
    float* __restrict__ C, int M, int N, int K)
{
    extern __shared__ float smem[];
    float* sAhi = smem;                        // [2][SA_FLOATS]
    float* sAlo = sAhi + 2 * SA_FLOATS;
    float* sBhi = sAlo + 2 * SA_FLOATS;        // [2][SB_FLOATS]
    float* sBlo = sBhi + 2 * SB_FLOATS;

    const int tid  = threadIdx.x;
    const int warp = tid >> 5;
    const int wm   = warp >> 1;                 // 0..3 -> m slab of 32
    const int wn   = warp & 1;                  // 0..1 -> n slab of 64
    const int m0 = blockIdx.y * 128, n0 = blockIdx.x * 128;

    // global load mapping
    const int arow = tid >> 1,  acol = (tid & 1) * 8;     // A: 128 x 16
    const int brow = tid >> 4,  bcol = (tid & 15) * 8;    // B: 16 x 128
    const float* Ap = A + (size_t)(m0 + arow) * K + acol;
    const float* Bp = B + (size_t)brow * N + n0 + bcol;

    wmma::fragment<wmma::accumulator, 16, 16, 8, float> acc[2][4];
    #pragma unroll
    for (int i = 0; i < 2; i++)
        #pragma unroll
        for (int j = 0; j < 4; j++) wmma::fill_fragment(acc[i][j], 0.0f);

    const int NITER = K / 16;
    float4 ra0, ra1, rb0, rb1;
    // prologue: prefetch iter 0
    ra0 = *(const float4*)(Ap);     ra1 = *(const float4*)(Ap + 4);
    rb0 = *(const float4*)(Bp);     rb1 = *(const float4*)(Bp + 4);

    for (int it = 0; it < NITER; ++it) {
        const int s = it & 1;
        // split + store current regs to stage s
        {
            float* ah = sAhi + s * SA_FLOATS + arow * LDA + acol;
            float* al = sAlo + s * SA_FLOATS + arow * LDA + acol;
            const float av[8] = {ra0.x, ra0.y, ra0.z, ra0.w, ra1.x, ra1.y, ra1.z, ra1.w};
            #pragma unroll
            for (int e = 0; e < 8; e++) { float h, l; tf32_split(av[e], h, l); ah[e] = h; al[e] = l; }
            float* bh = sBhi + s * SB_FLOATS + brow * LDB + bcol;
            float* bl = sBlo + s * SB_FLOATS + brow * LDB + bcol;
            const float bv[8] = {rb0.x, rb0.y, rb0.z, rb0.w, rb1.x, rb1.y, rb1.z, rb1.w};
            #pragma unroll
            for (int e = 0; e < 8; e++) { float h, l; tf32_split(bv[e], h, l); bh[e] = h; bl[e] = l; }
        }
        __syncthreads();

        // prefetch next iter
        if (it + 1 < NITER) {
            const int k0 = (it + 1) * 16;
            ra0 = *(const float4*)(Ap + k0);               ra1 = *(const float4*)(Ap + k0 + 4);
            rb0 = *(const float4*)(Bp + (size_t)k0 * N);   rb1 = *(const float4*)(Bp + (size_t)k0 * N + 4);
        }

        // compute: 2 k-steps of 8
        const float* pAh = sAhi + s * SA_FLOATS + (wm * 32) * LDA;
        const float* pAl = sAlo + s * SA_FLOATS + (wm * 32) * LDA;
        const float* pBh = sBhi + s * SB_FLOATS + wn * 64;
        const float* pBl = sBlo + s * SB_FLOATS + wn * 64;
        #pragma unroll
        for (int kk = 0; kk < 2; kk++) {
            wmma::fragment<wmma::matrix_a, 16, 16, 8, wmma::precision::tf32, wmma::row_major> ah[2], al[2];
            wmma::fragment<wmma::matrix_b, 16, 16, 8, wmma::precision::tf32, wmma::row_major> bh[4], bl[4];
            #pragma unroll
            for (int i = 0; i < 2; i++) {
                wmma::load_matrix_sync(ah[i], pAh + (i * 16) * LDA + kk * 8, LDA);
                wmma::load_matrix_sync(al[i], pAl + (i * 16) * LDA + kk * 8, LDA);
            }
            #pragma unroll
            for (int j = 0; j < 4; j++) {
                wmma::load_matrix_sync(bh[j], pBh + (kk * 8) * LDB + j * 16, LDB);
                wmma::load_matrix_sync(bl[j], pBl + (kk * 8) * LDB + j * 16, LDB);
            }
            #pragma unroll
            for (int i = 0; i < 2; i++)
                #pragma unroll
                for (int j = 0; j < 4; j++) {
                    wmma::mma_sync(acc[i][j], ah[i], bh[j], acc[i][j]);
                    wmma::mma_sync(acc[i][j], ah[i], bl[j], acc[i][j]);
                    wmma::mma_sync(acc[i][j], al[i], bh[j], acc[i][j]);
                }
        }
    }

    // epilogue: direct store to C
    #pragma unroll
    for (int i = 0; i < 2; i++)
        #pragma unroll
        for (int j = 0; j < 4; j++) {
            float* cp = C + (size_t)(m0 + wm * 32 + i * 16) * N + n0 + wn * 64 + j * 16;
            wmma::store_matrix_sync(cp, acc[i][j], N, wmma::mem_row_major);
        }
}

// =======================================================================
// bias add (row-broadcast), float4
// =======================================================================
__global__ void __launch_bounds__(256) bias_add_kernel(
    float* __restrict__ C, const float* __restrict__ bias)
{
    int i = blockIdx.x * 256 + threadIdx.x;     // over ROWS*DIM/4
    float4 c = ((float4*)C)[i];
    float4 b = ((const float4*)bias)[i & (DIM / 4 - 1)];
    c.x += b.x; c.y += b.y; c.z += b.z; c.w += b.w;
    ((float4*)C)[i] = c;
}

// =======================================================================
// Flash attention, fp32 (R1-passing version, verbatim)
// =======================================================================
__device__ __forceinline__ int swz(int d) { return ((d + (d >> 2)) * 2) & 63; }

__global__ void __launch_bounds__(256) attn_kernel(
    const float* __restrict__ Q, const float* __restrict__ KV,
    const float* __restrict__ MEMP, float* __restrict__ OUT)
{
    __shared__ float Qs[64 * 64];
    __shared__ float KVs[64 * 64];
    __shared__ float Ps[8][512];

    const int tid  = threadIdx.x;
    const int lane = tid & 31;
    const int warp = tid >> 5;
    const int qt = blockIdx.x, h = blockIdx.y, b = blockIdx.z;
    const int hcol  = h * DH;
    const int qrow0 = b * SEQ + qt * 64;
    const float scale = 0.125f;  // DH^-0.5

    #pragma unroll
    for (int i = 0; i < 4; i++) {
        int f = tid + i * 256;
        int r = f >> 4, d4 = (f & 15) * 4;
        float4 v = *(const float4*)(Q + (size_t)(qrow0 + r) * DIM + hcol + d4);
        v.x *= scale; v.y *= scale; v.z *= scale; v.w *= scale;
        *(float4*)&Qs[r * 64 + d4] = v;
    }

    float m[8], l[8], acc0[8], acc1[8];
    #pragma unroll
    for (int r = 0; r < 8; r++) { m[r] = -1e30f; l[r] = 0.f; acc0[r] = 0.f; acc1[r] = 0.f; }

    const int c0  = lane * 2;
    const int wr0 = warp * 8;

    for (int jt = 0; jt < KTOT / 64; jt++) {
        const int j0 = jt * 64;
        float4 kreg[4], vreg[4];
        #pragma unroll
        for (int i = 0; i < 4; i++) {
            int f = tid + i * 256;
            int c = f >> 4, d4 = (f & 15) * 4;
            if (j0 < SEQ) {
                const float* base = KV + (size_t)(b * SEQ + j0 + c) * (2 * DIM) + hcol + d4;
                kreg[i] = *(const float4*)base;
                vreg[i] = *(const float4*)(base + DIM);
            } else {
                const float* base = MEMP + (size_t)(b * MEMN + j0 - SEQ + c) * DIM + hcol + d4;
                kreg[i] = *(const float4*)base;
                vreg[i] = kreg[i];   // mem serves as both k and v
            }
        }
        __syncthreads();   // previous tile's PV done with KVs
        #pragma unroll
        for (int i = 0; i < 4; i++) {
            int f = tid + i * 256;
            int c = f >> 4, d4 = (f & 15) * 4;
            KVs[(d4 + 0) * 64 + (c ^ swz(d4 + 0))] = kreg[i].x;
            KVs[(d4 + 1) * 64 + (c ^ swz(d4 + 1))] = kreg[i].y;
            KVs[(d4 + 2) * 64 + (c ^ swz(d4 + 2))] = kreg[i].z;
            KVs[(d4 + 3) * 64 + (c ^ swz(d4 + 3))] = kreg[i].w;
        }
        __syncthreads();

        float s0[8], s1[8];
        #pragma unroll
        for (int r = 0; r < 8; r++) { s0[r] = 0.f; s1[r] = 0.f; }
        #pragma unroll
        for (int d4 = 0; d4 < 64; d4 += 4) {
            float2 kk[4];
            #pragma unroll
            for (int i = 0; i < 4; i++)
                kk[i] = *(const float2*)&KVs[(d4 + i) * 64 + (c0 ^ swz(d4 + i))];
            #pragma unroll
            for (int r = 0; r < 8; r++) {
                float4 qv = *(const float4*)&Qs[(wr0 + r) * 64 + d4];
                s0[r] += qv.x * kk[0].x; s0[r] += qv.y * kk[1].x;
                s0[r] += qv.z * kk[2].x; s0[r] += qv.w * kk[3].x;
                s1[r] += qv.x * kk[0].y; s1[r] += qv.y * kk[1].y;
                s1[r] += qv.z * kk[2].y; s1[r] += qv.w * kk[3].y;
            }
        }

        #pragma unroll
        for (int r = 0; r < 8; r++) {
            float tmax = fmaxf(s0[r], s1[r]);
            #pragma unroll
            for (int o = 16; o > 0; o >>= 1)
                tmax = fmaxf(tmax, __shfl_xor_sync(0xffffffffu, tmax, o));
            float mn = fmaxf(m[r], tmax);
            float p0 = __expf(s0[r] - mn);
            float p1 = __expf(s1[r] - mn);
            float rs = p0 + p1;
            #pragma unroll
            for (int o = 16; o > 0; o >>= 1)
                rs += __shfl_xor_sync(0xffffffffu, rs, o);
            float al = __expf(m[r] - mn);
            l[r] = l[r] * al + rs;
            m[r] = mn;
            acc0[r] *= al; acc1[r] *= al;
            *(float2*)&Ps[warp][r * 64 + c0] = make_float2(p0, p1);
        }

        __syncthreads();   // all warps done reading K^T from KVs
        #pragma unroll
        for (int i = 0; i < 4; i++) {
            int f = tid + i * 256;
            int c = f >> 4, d4 = (f & 15) * 4;
            *(float2*)&KVs[c * 64 + d4]     = make_float2(vreg[i].x, vreg[i].y);
            *(float2*)&KVs[c * 64 + d4 + 2] = make_float2(vreg[i].z, vreg[i].w);
        }
        __syncthreads();

        #pragma unroll
        for (int c4 = 0; c4 < 64; c4 += 4) {
            float2 vv[4];
            #pragma unroll
            for (int i = 0; i < 4; i++)
                vv[i] = *(const float2*)&KVs[(c4 + i) * 64 + c0];
            #pragma unroll
            for (int r = 0; r < 8; r++) {
                float4 p = *(const float4*)&Ps[warp][r * 64 + c4];
                acc0[r] += p.x * vv[0].x; acc0[r] += p.y * vv[1].x;
                acc0[r] += p.z * vv[2].x; acc0[r] += p.w * vv[3].x;
                acc1[r] += p.x * vv[0].y; acc1[r] += p.y * vv[1].y;
                acc1[r] += p.z * vv[2].y; acc1[r] += p.w * vv[3].y;
            }
        }
    }

    #pragma unroll
    for (int r = 0; r < 8; r++) {
        float inv = 1.0f / l[r];
        *(float2*)&OUT[(size_t)(qrow0 + wr0 + r) * DIM + hcol + c0] =
            make_float2(acc0[r] * inv, acc1[r] * inv);
    }
}

// =======================================================================
// launch
// =======================================================================
extern "C" void kernel_launch(void* const* d_in, const int* in_sizes, int n_in,
                              void* d_out, int out_size)
{
    const float* x        = (const float*)d_in[0];
    const float* memories = (const float*)d_in[1];
    const float* ln_g     = (const float*)d_in[2];
    const float* ln_b     = (const float*)d_in[3];
    const float* Wq       = (const float*)d_in[4];
    const float* Wkv      = (const float*)d_in[5];
    const float* Wm       = (const float*)d_in[6];
    const float* Wo       = (const float*)d_in[7];
    const float* bo       = (const float*)d_in[8];
    float* out = (float*)d_out;

    float *p_xn, *p_q, *p_kv, *p_mem, *p_att;
    cudaGetSymbolAddress((void**)&p_xn,  g_xn);
    cudaGetSymbolAddress((void**)&p_q,   g_q);
    cudaGetSymbolAddress((void**)&p_kv,  g_kv);
    cudaGetSymbolAddress((void**)&p_mem, g_mem);
    cudaGetSymbolAddress((void**)&p_att, g_att);

    cudaFuncSetAttribute(gemm_wmma3x, cudaFuncAttributeMaxDynamicSharedMemorySize, GSMEM);

    // 1. LayerNorm(x) -> xn
    ln_kernel<<<ROWS, 256>>>(x, ln_g, ln_b, p_xn);

    // 2. projections (WMMA tf32 3x)
    gemm_wmma3x<<<dim3(DIM / 128,     ROWS / 128),  256, GSMEM>>>(p_xn, Wq,  p_q,  ROWS,  DIM,     DIM);
    gemm_wmma3x<<<dim3(2 * DIM / 128, ROWS / 128),  256, GSMEM>>>(p_xn, Wkv, p_kv, ROWS,  2 * DIM, DIM);
    gemm_wmma3x<<<dim3(DIM / 128,     MROWS / 128), 256, GSMEM>>>(memories, Wm, p_mem, MROWS, DIM, DIM);

    // 3. attention
    attn_kernel<<<dim3(SEQ / 64, HEADS, BATCH), 256>>>(p_q, p_kv, p_mem, p_att);

    // 4. output projection -> d_out, then bias
    gemm_wmma3x<<<dim3(DIM / 128, ROWS / 128), 256, GSMEM>>>(p_att, Wo, out, ROWS, DIM, DIM);
    bias_add_kernel<<<ROWS * DIM / 4 / 256, 256>>>(out, bo);
}